// round 12
// baseline (speedup 1.0000x reference)
#include <cuda_runtime.h>
#include <cuda_bf16.h>
#include <cstdint>

#define NB 32
#define NM 2048
#define ND 1024
#define TM 256               // score m-tile
#define TH 128               // score h-tile
#define KE 64                // k elems per stage
#define NS 128               // stages = (ND/KE) * (ND/TH)
#define STRH 72              // smem row stride in halves (144B) -> conflict-free
#define A_ST (256 * STRH * 2)            // 36864
#define B_ST (128 * STRH * 2)            // 18432
#define STG (A_ST + B_ST)                // 55296
#define SC_SMEM (3 * STG)                // 165888

// scratch
__device__ float g_qp[NB * ND];
__device__ float g_ctx[NB * ND];
__device__ float g_ctxp[NB * 32 * ND];
__device__ __nv_bfloat16 g_kbf[(size_t)NB * NM * ND];   // keys in bf16
__device__ __nv_bfloat16 g_wkbf[ND * ND];               // W_key in bf16

// ---------------- helpers ------------------------------------------------
__device__ __forceinline__ int load_len(const int* __restrict__ L, int b) {
    bool is64 = (L[1] == 0) && (L[3] == 0) && (L[5] == 0);
    return is64 ? L[2 * b] : L[b];
}
__device__ __forceinline__ float tanh_fast(float x) {
    float r; asm("tanh.approx.f32 %0, %1;" : "=f"(r) : "f"(x)); return r;
}
__device__ __forceinline__ unsigned int smem_u32(const void* p) {
    unsigned int a;
    asm("{ .reg .u64 t; cvta.to.shared.u64 t, %1; cvt.u32.u64 %0, t; }" : "=r"(a) : "l"(p));
    return a;
}
__device__ __forceinline__ void cpasync16(unsigned int dst, const void* src) {
    asm volatile("cp.async.cg.shared.global [%0], [%1], 16;" :: "r"(dst), "l"(src) : "memory");
}
__device__ __forceinline__ void ldsm4(unsigned int& r0, unsigned int& r1,
                                      unsigned int& r2, unsigned int& r3,
                                      unsigned int addr) {
    asm volatile("ldmatrix.sync.aligned.m8n8.x4.shared.b16 {%0,%1,%2,%3}, [%4];"
                 : "=r"(r0), "=r"(r1), "=r"(r2), "=r"(r3) : "r"(addr));
}
__device__ __forceinline__ void mma_bf16(float d[4], const unsigned int a[4],
                                         const unsigned int b[2]) {
    asm volatile(
        "mma.sync.aligned.m16n8k16.row.col.f32.bf16.bf16.f32 "
        "{%0,%1,%2,%3}, {%4,%5,%6,%7}, {%8,%9}, {%0,%1,%2,%3};"
        : "+f"(d[0]), "+f"(d[1]), "+f"(d[2]), "+f"(d[3])
        : "r"(a[0]), "r"(a[1]), "r"(a[2]), "r"(a[3]), "r"(b[0]), "r"(b[1]));
}

// ---------------- Kernel 0a: keys fp32 -> bf16, length-aware -------------
__global__ void conv_keys_kernel(const float* __restrict__ src,
                                 __nv_bfloat16* __restrict__ dst,
                                 const int* __restrict__ lens) {
    int b = blockIdx.x >> 5;          // 32 chunks of 64 rows each
    int p = blockIdx.x & 31;
    if (p * 64 >= load_len(lens, b)) return;   // fully-masked chunk: skip
    size_t base8 = (((size_t)b * NM + (size_t)p * 64) * ND) >> 3;  // in 8-elem units
    const float4* s4 = (const float4*)src;
    uint4* d4 = (uint4*)dst;
    #pragma unroll 4
    for (int i = threadIdx.x; i < 64 * ND / 8; i += 256) {
        size_t j = base8 + i;
        float4 a = __ldg(&s4[2 * j]);
        float4 bb = __ldg(&s4[2 * j + 1]);
        __nv_bfloat162 p0 = __float22bfloat162_rn(make_float2(a.x, a.y));
        __nv_bfloat162 p1 = __float22bfloat162_rn(make_float2(a.z, a.w));
        __nv_bfloat162 p2 = __float22bfloat162_rn(make_float2(bb.x, bb.y));
        __nv_bfloat162 p3 = __float22bfloat162_rn(make_float2(bb.z, bb.w));
        uint4 o;
        o.x = *(unsigned int*)&p0; o.y = *(unsigned int*)&p1;
        o.z = *(unsigned int*)&p2; o.w = *(unsigned int*)&p3;
        d4[j] = o;
    }
}

// ---------------- Kernel 0b: generic fp32 -> bf16 (for Wk) ---------------
__global__ void conv_kernel(const float* __restrict__ src,
                            __nv_bfloat16* __restrict__ dst, int n8) {
    int i = blockIdx.x * blockDim.x + threadIdx.x;
    if (i >= n8) return;
    const float4* s4 = (const float4*)src;
    float4 a = __ldg(&s4[2 * i]);
    float4 b = __ldg(&s4[2 * i + 1]);
    __nv_bfloat162 p0 = __float22bfloat162_rn(make_float2(a.x, a.y));
    __nv_bfloat162 p1 = __float22bfloat162_rn(make_float2(a.z, a.w));
    __nv_bfloat162 p2 = __float22bfloat162_rn(make_float2(b.x, b.y));
    __nv_bfloat162 p3 = __float22bfloat162_rn(make_float2(b.z, b.w));
    uint4 o;
    o.x = *(unsigned int*)&p0; o.y = *(unsigned int*)&p1;
    o.z = *(unsigned int*)&p2; o.w = *(unsigned int*)&p3;
    ((uint4*)dst)[i] = o;
}

// ---------------- Kernel 1: q projection (Wq read once) ------------------
__global__ void qproj_kernel(const float* __restrict__ q,
                             const float* __restrict__ Wq) {
    int h = blockIdx.x * 8 + (threadIdx.x >> 5);
    int lane = threadIdx.x & 31;
    float wq[32];
    const float* wr = Wq + (size_t)h * ND;
    #pragma unroll
    for (int j = 0; j < 32; ++j) wq[j] = __ldg(&wr[lane + 32 * j]);
    for (int b = 0; b < NB; ++b) {
        const float* qr = q + (size_t)b * ND;
        float acc = 0.f;
        #pragma unroll
        for (int j = 0; j < 32; ++j) acc += __ldg(&qr[lane + 32 * j]) * wq[j];
        #pragma unroll
        for (int o = 16; o; o >>= 1) acc += __shfl_down_sync(0xffffffffu, acc, o);
        if (lane == 0) g_qp[b * ND + h] = acc;
    }
}

// ---------------- Kernel 2: bf16 mma.sync score GEMM ---------------------
// 256m x 128h CTA tile, 8 warps as 4(m) x 2(n), warp tile 64x64.
// ldmatrix.x4 operand loads + register double-buffered k-steps.
__device__ __forceinline__ void load_stage(unsigned int sbase,
                                           const __nv_bfloat16* __restrict__ keysB,
                                           int m0, int s, int tid) {
    int hc = s >> 4, kt = s & 15, bf = s % 3;
    int k0 = kt * KE;
    unsigned int abase = sbase + bf * STG;
    unsigned int bbase = abase + A_ST;
    #pragma unroll
    for (int i = 0; i < 8; ++i) {
        int idx = i * 256 + tid;
        int r = idx >> 3, c = idx & 7;
        cpasync16(abase + (unsigned)(r * 144 + c * 16),
                  keysB + (size_t)(m0 + r) * ND + k0 + c * 8);
    }
    #pragma unroll
    for (int i = 0; i < 4; ++i) {
        int idx = i * 256 + tid;
        int r = idx >> 3, c = idx & 7;
        cpasync16(bbase + (unsigned)(r * 144 + c * 16),
                  g_wkbf + (size_t)(hc * 128 + r) * ND + k0 + c * 8);
    }
    asm volatile("cp.async.commit_group;" ::: "memory");
}

__global__ void __launch_bounds__(256, 1)
score_kernel(const float* __restrict__ We,
             const int* __restrict__ lens,
             float* __restrict__ attn_out) {
    int b = blockIdx.y;
    int m0 = blockIdx.x * TM;
    int len = load_len(lens, b);
    if (m0 >= len) return;

    extern __shared__ char smem[];
    unsigned int sbase = smem_u32(smem);
    int tid = threadIdx.x, lane = tid & 31, wid = tid >> 5;
    int wm = wid >> 1, wn = wid & 1;
    const __nv_bfloat16* keysB = g_kbf + (size_t)b * NM * ND;

    // per-thread ldmatrix base offsets (bytes, stage-local)
    unsigned int aoff = (unsigned)((wm * 64 + (lane & 7) + ((lane >> 3) & 1) * 8) * 144
                                   + ((lane >> 4) & 1) * 16);
    unsigned int boff = (unsigned)(A_ST + (wn * 64 + (lane & 7) + ((lane >> 4) & 1) * 8) * 144
                                   + ((lane >> 3) & 1) * 16);

    float d[4][8][4];
    float sp[4][2];
    unsigned int ua[2][4][4], ub[2][8][2];
    #pragma unroll
    for (int mf = 0; mf < 4; ++mf) { sp[mf][0] = 0.f; sp[mf][1] = 0.f; }

    load_stage(sbase, keysB, m0, 0, tid);
    load_stage(sbase, keysB, m0, 1, tid);

    for (int s = 0; s < NS; ++s) {
        if (s + 2 < NS) asm volatile("cp.async.wait_group 1;" ::: "memory");
        else            asm volatile("cp.async.wait_group 0;" ::: "memory");
        __syncthreads();
        if (s + 2 < NS) load_stage(sbase, keysB, m0, s + 2, tid);

        int bf = s % 3, kt = s & 15, hc = s >> 4;
        unsigned int stg = sbase + bf * STG;

        if (kt == 0) {
            #pragma unroll
            for (int mf = 0; mf < 4; ++mf)
                #pragma unroll
                for (int nf = 0; nf < 8; ++nf)
                    #pragma unroll
                    for (int e = 0; e < 4; ++e) d[mf][nf][e] = 0.f;
        }

        // prefetch ks=0 fragments
        #pragma unroll
        for (int mf = 0; mf < 4; ++mf)
            ldsm4(ua[0][mf][0], ua[0][mf][1], ua[0][mf][2], ua[0][mf][3],
                  stg + aoff + (unsigned)(mf * 16 * 144));
        #pragma unroll
        for (int pr = 0; pr < 4; ++pr)
            ldsm4(ub[0][2 * pr][0], ub[0][2 * pr][1],
                  ub[0][2 * pr + 1][0], ub[0][2 * pr + 1][1],
                  stg + boff + (unsigned)(pr * 16 * 144));

        #pragma unroll
        for (int ks = 0; ks < 4; ++ks) {
            int cur = ks & 1, nxt = cur ^ 1;
            if (ks < 3) {
                unsigned int cofs = (unsigned)((ks + 1) * 32);
                #pragma unroll
                for (int mf = 0; mf < 4; ++mf)
                    ldsm4(ua[nxt][mf][0], ua[nxt][mf][1], ua[nxt][mf][2], ua[nxt][mf][3],
                          stg + aoff + (unsigned)(mf * 16 * 144) + cofs);
                #pragma unroll
                for (int pr = 0; pr < 4; ++pr)
                    ldsm4(ub[nxt][2 * pr][0], ub[nxt][2 * pr][1],
                          ub[nxt][2 * pr + 1][0], ub[nxt][2 * pr + 1][1],
                          stg + boff + (unsigned)(pr * 16 * 144) + cofs);
            }
            #pragma unroll
            for (int mf = 0; mf < 4; ++mf)
                #pragma unroll
                for (int nf = 0; nf < 8; ++nf)
                    mma_bf16(d[mf][nf], ua[cur][mf], ub[cur][nf]);
        }

        if (kt == 15) {
            int hbase = hc * 128 + wn * 64 + 2 * (lane & 3);
            #pragma unroll
            for (int nf = 0; nf < 8; ++nf) {
                float qv0 = __ldg(&g_qp[b * ND + hbase + nf * 8]);
                float qv1 = __ldg(&g_qp[b * ND + hbase + nf * 8 + 1]);
                float we0 = __ldg(&We[hbase + nf * 8]);
                float we1 = __ldg(&We[hbase + nf * 8 + 1]);
                #pragma unroll
                for (int mf = 0; mf < 4; ++mf) {
                    sp[mf][0] += tanh_fast(d[mf][nf][0] + qv0) * we0;
                    sp[mf][0] += tanh_fast(d[mf][nf][1] + qv1) * we1;
                    sp[mf][1] += tanh_fast(d[mf][nf][2] + qv0) * we0;
                    sp[mf][1] += tanh_fast(d[mf][nf][3] + qv1) * we1;
                }
            }
        }
    }

    // cross-lane reduction via smem [256][9]
    __syncthreads();
    float* sred = (float*)smem;
    int col = wn * 4 + (lane & 3);
    #pragma unroll
    for (int mf = 0; mf < 4; ++mf)
        #pragma unroll
        for (int rb = 0; rb < 2; ++rb) {
            int r = wm * 64 + mf * 16 + (lane >> 2) + 8 * rb;
            sred[r * 9 + col] = sp[mf][rb];
        }
    __syncthreads();
    {
        float sacc = 0.f;
        #pragma unroll
        for (int j = 0; j < 8; ++j) sacc += sred[tid * 9 + j];
        attn_out[(size_t)b * NM + m0 + tid] = sacc;
    }
}

// ---------------- Kernel 3: masked softmax (in-place) --------------------
__global__ void softmax_kernel(const int* __restrict__ lens,
                               float* __restrict__ attn) {
    int b = blockIdx.x;
    int len = load_len(lens, b);
    float* row = attn + (size_t)b * NM;
    __shared__ float red[256];
    int tid = threadIdx.x;

    float mx = -3.0e38f;
    for (int m = tid; m < len; m += 256) mx = fmaxf(mx, row[m]);
    red[tid] = mx; __syncthreads();
    for (int s = 128; s; s >>= 1) {
        if (tid < s) red[tid] = fmaxf(red[tid], red[tid + s]);
        __syncthreads();
    }
    mx = red[0]; __syncthreads();

    float sm = 0.f;
    for (int m = tid; m < len; m += 256) sm += expf(row[m] - mx);
    red[tid] = sm; __syncthreads();
    for (int s = 128; s; s >>= 1) {
        if (tid < s) red[tid] += red[tid + s];
        __syncthreads();
    }
    float inv = 1.f / red[0];
    __syncthreads();

    for (int m = tid; m < NM; m += 256) {
        float w = (m < len) ? expf(row[m] - mx) * inv : 0.f;
        row[m] = w;
    }
}

// ---------------- Kernel 4: ctx partials (32 chunks x 64 rows, float4) ---
__global__ void ctx_kernel(const float* __restrict__ values,
                           const int* __restrict__ lens,
                           const float* __restrict__ attn) {
    int b = blockIdx.x >> 5;
    int p = blockIdx.x & 31;
    int len = load_len(lens, b);
    int mstart = p * 64;
    int mend = min(mstart + 64, len);
    int tid = threadIdx.x;

    __shared__ float sw[64];
    float4 acc = make_float4(0.f, 0.f, 0.f, 0.f);
    if (mstart < mend) {
        if (tid < 64) {
            int mm = mstart + tid;
            sw[tid] = (mm < mend) ? attn[(size_t)b * NM + mm] : 0.f;
        }
        __syncthreads();
        const float4* vb4 = (const float4*)(values + (size_t)b * NM * ND);
        int lim = mend - mstart;
        #pragma unroll 8
        for (int t = 0; t < lim; ++t) {
            float w = sw[t];
            float4 v = __ldg(&vb4[(size_t)(mstart + t) * (ND / 4) + tid]);
            acc.x += w * v.x; acc.y += w * v.y;
            acc.z += w * v.z; acc.w += w * v.w;
        }
    }
    ((float4*)g_ctxp)[((size_t)b * 32 + p) * (ND / 4) + tid] = acc;
}

// ---------------- Kernel 5: reduce partials ------------------------------
__global__ void reduce_ctx_kernel() {
    int b = blockIdx.x;
    int d = threadIdx.x;
    float4 s = make_float4(0.f, 0.f, 0.f, 0.f);
    #pragma unroll
    for (int p = 0; p < 32; ++p) {
        float4 v = ((const float4*)g_ctxp)[((size_t)b * 32 + p) * (ND / 4) + d];
        s.x += v.x; s.y += v.y; s.z += v.z; s.w += v.w;
    }
    ((float4*)g_ctx)[(size_t)b * (ND / 4) + d] = s;
}

// ---------------- Kernel 6: output projection (Wk read once) -------------
__global__ void outproj_kernel(const float* __restrict__ Wk,
                               float* __restrict__ out) {
    int h = blockIdx.x * 8 + (threadIdx.x >> 5);
    int lane = threadIdx.x & 31;
    float wk[32];
    const float* wr = Wk + (size_t)h * ND;
    #pragma unroll
    for (int j = 0; j < 32; ++j) wk[j] = __ldg(&wr[lane + 32 * j]);
    for (int b = 0; b < NB; ++b) {
        const float* xr = g_ctx + (size_t)b * ND;
        float acc = 0.f;
        #pragma unroll
        for (int j = 0; j < 32; ++j) acc += xr[lane + 32 * j] * wk[j];
        #pragma unroll
        for (int o = 16; o; o >>= 1) acc += __shfl_down_sync(0xffffffffu, acc, o);
        if (lane == 0) out[b * ND + h] = acc;
    }
}

// ---------------- launch -------------------------------------------------
extern "C" void kernel_launch(void* const* d_in, const int* in_sizes, int n_in,
                              void* d_out, int out_size) {
    const float* queries = (const float*)d_in[0];
    const float* keys    = (const float*)d_in[1];
    const float* values  = (const float*)d_in[2];
    const int*   lens    = (const int*)d_in[3];
    const float* Wk      = (const float*)d_in[4];
    const float* Wq      = (const float*)d_in[5];
    const float* We      = (const float*)d_in[6];

    float* out      = (float*)d_out;
    float* out_val  = out;             // [B,1,D]
    float* out_attn = out + NB * ND;   // [B,1,M]

    static bool attr_set = false;
    if (!attr_set) {
        cudaFuncSetAttribute(score_kernel,
                             cudaFuncAttributeMaxDynamicSharedMemorySize, SC_SMEM);
        attr_set = true;
    }

    __nv_bfloat16* kbf;  cudaGetSymbolAddress((void**)&kbf, g_kbf);
    __nv_bfloat16* wkbf; cudaGetSymbolAddress((void**)&wkbf, g_wkbf);

    conv_keys_kernel<<<NB * 32, 256>>>(keys, kbf, lens);
    conv_kernel     <<<(ND * ND / 8 + 255) / 256, 256>>>(Wk, wkbf, ND * ND / 8);
    qproj_kernel    <<<ND / 8, 256>>>(queries, Wq);
    score_kernel    <<<dim3(NM / TM, NB), 256, SC_SMEM>>>(We, lens, out_attn);
    softmax_kernel  <<<NB, 256>>>(lens, out_attn);
    ctx_kernel      <<<NB * 32, 256>>>(values, lens, out_attn);
    reduce_ctx_kernel<<<NB, 256>>>();
    outproj_kernel  <<<ND / 8, 256>>>(Wk, out_val);
}

// round 14
// speedup vs baseline: 1.4039x; 1.4039x over previous
#include <cuda_runtime.h>
#include <cuda_bf16.h>
#include <cstdint>

#define NB 32
#define NM 2048
#define ND 1024
#define TM 256               // score m-tile
#define TH 128               // score h-tile
#define KE 64                // k elems per stage
#define NS 128               // stages = (ND/KE) * (ND/TH)
#define STRH 72              // smem row stride in halves (144B) -> conflict-free
#define A_ST (256 * STRH * 2)            // 36864
#define B_ST (128 * STRH * 2)            // 18432
#define STG (A_ST + B_ST)                // 55296
#define SC_SMEM (3 * STG)                // 165888

// scratch
__device__ float g_qp[NB * ND];
__device__ float g_ctx[NB * ND];
__device__ float g_ctxp[NB * 32 * ND];
__device__ __nv_bfloat16 g_kbf[(size_t)NB * NM * ND];   // keys in bf16
__device__ __nv_bfloat16 g_wkbf[ND * ND];               // W_key in bf16

// ---------------- helpers ------------------------------------------------
__device__ __forceinline__ int load_len(const int* __restrict__ L, int b) {
    bool is64 = (L[1] == 0) && (L[3] == 0) && (L[5] == 0);
    return is64 ? L[2 * b] : L[b];
}
__device__ __forceinline__ float tanh_fast(float x) {
    float r; asm("tanh.approx.f32 %0, %1;" : "=f"(r) : "f"(x)); return r;
}
__device__ __forceinline__ unsigned int smem_u32(const void* p) {
    unsigned int a;
    asm("{ .reg .u64 t; cvta.to.shared.u64 t, %1; cvt.u32.u64 %0, t; }" : "=r"(a) : "l"(p));
    return a;
}
__device__ __forceinline__ void cpasync16(unsigned int dst, const void* src) {
    asm volatile("cp.async.cg.shared.global [%0], [%1], 16;" :: "r"(dst), "l"(src) : "memory");
}
__device__ __forceinline__ void ldsm4(unsigned int& r0, unsigned int& r1,
                                      unsigned int& r2, unsigned int& r3,
                                      unsigned int addr) {
    asm volatile("ldmatrix.sync.aligned.m8n8.x4.shared.b16 {%0,%1,%2,%3}, [%4];"
                 : "=r"(r0), "=r"(r1), "=r"(r2), "=r"(r3) : "r"(addr));
}
__device__ __forceinline__ void mma_bf16(float d[4], const unsigned int a[4],
                                         const unsigned int b[2]) {
    asm volatile(
        "mma.sync.aligned.m16n8k16.row.col.f32.bf16.bf16.f32 "
        "{%0,%1,%2,%3}, {%4,%5,%6,%7}, {%8,%9}, {%0,%1,%2,%3};"
        : "+f"(d[0]), "+f"(d[1]), "+f"(d[2]), "+f"(d[3])
        : "r"(a[0]), "r"(a[1]), "r"(a[2]), "r"(a[3]), "r"(b[0]), "r"(b[1]));
}

// ---------------- Kernel 0a: keys fp32 -> bf16, length-aware -------------
__global__ void conv_keys_kernel(const float* __restrict__ src,
                                 __nv_bfloat16* __restrict__ dst,
                                 const int* __restrict__ lens) {
    int b = blockIdx.x >> 5;          // 32 chunks of 64 rows each
    int p = blockIdx.x & 31;
    if (p * 64 >= load_len(lens, b)) return;   // fully-masked chunk: skip
    size_t base8 = (((size_t)b * NM + (size_t)p * 64) * ND) >> 3;  // in 8-elem units
    const float4* s4 = (const float4*)src;
    uint4* d4 = (uint4*)dst;
    #pragma unroll 4
    for (int i = threadIdx.x; i < 64 * ND / 8; i += 256) {
        size_t j = base8 + i;
        float4 a = __ldg(&s4[2 * j]);
        float4 bb = __ldg(&s4[2 * j + 1]);
        __nv_bfloat162 p0 = __float22bfloat162_rn(make_float2(a.x, a.y));
        __nv_bfloat162 p1 = __float22bfloat162_rn(make_float2(a.z, a.w));
        __nv_bfloat162 p2 = __float22bfloat162_rn(make_float2(bb.x, bb.y));
        __nv_bfloat162 p3 = __float22bfloat162_rn(make_float2(bb.z, bb.w));
        uint4 o;
        o.x = *(unsigned int*)&p0; o.y = *(unsigned int*)&p1;
        o.z = *(unsigned int*)&p2; o.w = *(unsigned int*)&p3;
        d4[j] = o;
    }
}

// ---------------- Kernel 0b: generic fp32 -> bf16 (for Wk) ---------------
__global__ void conv_kernel(const float* __restrict__ src,
                            __nv_bfloat16* __restrict__ dst, int n8) {
    int i = blockIdx.x * blockDim.x + threadIdx.x;
    if (i >= n8) return;
    const float4* s4 = (const float4*)src;
    float4 a = __ldg(&s4[2 * i]);
    float4 b = __ldg(&s4[2 * i + 1]);
    __nv_bfloat162 p0 = __float22bfloat162_rn(make_float2(a.x, a.y));
    __nv_bfloat162 p1 = __float22bfloat162_rn(make_float2(a.z, a.w));
    __nv_bfloat162 p2 = __float22bfloat162_rn(make_float2(b.x, b.y));
    __nv_bfloat162 p3 = __float22bfloat162_rn(make_float2(b.z, b.w));
    uint4 o;
    o.x = *(unsigned int*)&p0; o.y = *(unsigned int*)&p1;
    o.z = *(unsigned int*)&p2; o.w = *(unsigned int*)&p3;
    ((uint4*)dst)[i] = o;
}

// ---------------- Kernel 1: q projection (Wq read once) ------------------
__global__ void qproj_kernel(const float* __restrict__ q,
                             const float* __restrict__ Wq) {
    int h = blockIdx.x * 8 + (threadIdx.x >> 5);
    int lane = threadIdx.x & 31;
    float wq[32];
    const float* wr = Wq + (size_t)h * ND;
    #pragma unroll
    for (int j = 0; j < 32; ++j) wq[j] = __ldg(&wr[lane + 32 * j]);
    for (int b = 0; b < NB; ++b) {
        const float* qr = q + (size_t)b * ND;
        float acc = 0.f;
        #pragma unroll
        for (int j = 0; j < 32; ++j) acc += __ldg(&qr[lane + 32 * j]) * wq[j];
        #pragma unroll
        for (int o = 16; o; o >>= 1) acc += __shfl_down_sync(0xffffffffu, acc, o);
        if (lane == 0) g_qp[b * ND + h] = acc;
    }
}

// ---------------- Kernel 2: bf16 mma.sync score GEMM ---------------------
// 256m x 128h CTA tile, 8 warps as 4(m) x 2(n), warp tile 64x64.
// ldmatrix.x4 operand loads, single-buffered (register budget!).
__device__ __forceinline__ void load_stage(unsigned int sbase,
                                           const __nv_bfloat16* __restrict__ keysB,
                                           int m0, int s, int tid) {
    int hc = s >> 4, kt = s & 15, bf = s % 3;
    int k0 = kt * KE;
    unsigned int abase = sbase + bf * STG;
    unsigned int bbase = abase + A_ST;
    #pragma unroll
    for (int i = 0; i < 8; ++i) {
        int idx = i * 256 + tid;
        int r = idx >> 3, c = idx & 7;
        cpasync16(abase + (unsigned)(r * 144 + c * 16),
                  keysB + (size_t)(m0 + r) * ND + k0 + c * 8);
    }
    #pragma unroll
    for (int i = 0; i < 4; ++i) {
        int idx = i * 256 + tid;
        int r = idx >> 3, c = idx & 7;
        cpasync16(bbase + (unsigned)(r * 144 + c * 16),
                  g_wkbf + (size_t)(hc * 128 + r) * ND + k0 + c * 8);
    }
    asm volatile("cp.async.commit_group;" ::: "memory");
}

__global__ void __launch_bounds__(256, 1)
score_kernel(const float* __restrict__ We,
             const int* __restrict__ lens,
             float* __restrict__ attn_out) {
    int b = blockIdx.y;
    int m0 = blockIdx.x * TM;
    int len = load_len(lens, b);
    if (m0 >= len) return;

    extern __shared__ char smem[];
    unsigned int sbase = smem_u32(smem);
    int tid = threadIdx.x, lane = tid & 31, wid = tid >> 5;
    int wm = wid >> 1, wn = wid & 1;
    const __nv_bfloat16* keysB = g_kbf + (size_t)b * NM * ND;

    // per-thread ldmatrix base offsets (bytes, stage-local)
    unsigned int aoff = (unsigned)((wm * 64 + (lane & 7) + ((lane >> 3) & 1) * 8) * 144
                                   + ((lane >> 4) & 1) * 16);
    unsigned int boff = (unsigned)(A_ST + (wn * 64 + (lane & 7) + ((lane >> 4) & 1) * 8) * 144
                                   + ((lane >> 3) & 1) * 16);

    float d[4][8][4];
    float sp[4][2];
    #pragma unroll
    for (int mf = 0; mf < 4; ++mf) { sp[mf][0] = 0.f; sp[mf][1] = 0.f; }

    load_stage(sbase, keysB, m0, 0, tid);
    load_stage(sbase, keysB, m0, 1, tid);

    for (int s = 0; s < NS; ++s) {
        if (s + 2 < NS) asm volatile("cp.async.wait_group 1;" ::: "memory");
        else            asm volatile("cp.async.wait_group 0;" ::: "memory");
        __syncthreads();
        if (s + 2 < NS) load_stage(sbase, keysB, m0, s + 2, tid);

        int bf = s % 3, kt = s & 15, hc = s >> 4;
        unsigned int stg = sbase + bf * STG;

        if (kt == 0) {
            #pragma unroll
            for (int mf = 0; mf < 4; ++mf)
                #pragma unroll
                for (int nf = 0; nf < 8; ++nf)
                    #pragma unroll
                    for (int e = 0; e < 4; ++e) d[mf][nf][e] = 0.f;
        }

        #pragma unroll
        for (int ks = 0; ks < 4; ++ks) {
            unsigned int cofs = (unsigned)(ks * 32);
            unsigned int ua[4][4], ub[8][2];
            #pragma unroll
            for (int mf = 0; mf < 4; ++mf)
                ldsm4(ua[mf][0], ua[mf][1], ua[mf][2], ua[mf][3],
                      stg + aoff + (unsigned)(mf * 16 * 144) + cofs);
            #pragma unroll
            for (int pr = 0; pr < 4; ++pr)
                ldsm4(ub[2 * pr][0], ub[2 * pr][1],
                      ub[2 * pr + 1][0], ub[2 * pr + 1][1],
                      stg + boff + (unsigned)(pr * 16 * 144) + cofs);
            #pragma unroll
            for (int mf = 0; mf < 4; ++mf)
                #pragma unroll
                for (int nf = 0; nf < 8; ++nf)
                    mma_bf16(d[mf][nf], ua[mf], ub[nf]);
        }

        if (kt == 15) {
            int hbase = hc * 128 + wn * 64 + 2 * (lane & 3);
            #pragma unroll
            for (int nf = 0; nf < 8; ++nf) {
                float qv0 = __ldg(&g_qp[b * ND + hbase + nf * 8]);
                float qv1 = __ldg(&g_qp[b * ND + hbase + nf * 8 + 1]);
                float we0 = __ldg(&We[hbase + nf * 8]);
                float we1 = __ldg(&We[hbase + nf * 8 + 1]);
                #pragma unroll
                for (int mf = 0; mf < 4; ++mf) {
                    sp[mf][0] += tanh_fast(d[mf][nf][0] + qv0) * we0;
                    sp[mf][0] += tanh_fast(d[mf][nf][1] + qv1) * we1;
                    sp[mf][1] += tanh_fast(d[mf][nf][2] + qv0) * we0;
                    sp[mf][1] += tanh_fast(d[mf][nf][3] + qv1) * we1;
                }
            }
        }
    }

    // cross-lane reduction via smem [256][9]
    __syncthreads();
    float* sred = (float*)smem;
    int col = wn * 4 + (lane & 3);
    #pragma unroll
    for (int mf = 0; mf < 4; ++mf)
        #pragma unroll
        for (int rb = 0; rb < 2; ++rb) {
            int r = wm * 64 + mf * 16 + (lane >> 2) + 8 * rb;
            sred[r * 9 + col] = sp[mf][rb];
        }
    __syncthreads();
    {
        float sacc = 0.f;
        #pragma unroll
        for (int j = 0; j < 8; ++j) sacc += sred[tid * 9 + j];
        attn_out[(size_t)b * NM + m0 + tid] = sacc;
    }
}

// ---------------- Kernel 3: masked softmax (in-place) --------------------
__global__ void softmax_kernel(const int* __restrict__ lens,
                               float* __restrict__ attn) {
    int b = blockIdx.x;
    int len = load_len(lens, b);
    float* row = attn + (size_t)b * NM;
    __shared__ float red[256];
    int tid = threadIdx.x;

    float mx = -3.0e38f;
    for (int m = tid; m < len; m += 256) mx = fmaxf(mx, row[m]);
    red[tid] = mx; __syncthreads();
    for (int s = 128; s; s >>= 1) {
        if (tid < s) red[tid] = fmaxf(red[tid], red[tid + s]);
        __syncthreads();
    }
    mx = red[0]; __syncthreads();

    float sm = 0.f;
    for (int m = tid; m < len; m += 256) sm += expf(row[m] - mx);
    red[tid] = sm; __syncthreads();
    for (int s = 128; s; s >>= 1) {
        if (tid < s) red[tid] += red[tid + s];
        __syncthreads();
    }
    float inv = 1.f / red[0];
    __syncthreads();

    for (int m = tid; m < NM; m += 256) {
        float w = (m < len) ? expf(row[m] - mx) * inv : 0.f;
        row[m] = w;
    }
}

// ---------------- Kernel 4: ctx partials (32 chunks x 64 rows, float4) ---
__global__ void ctx_kernel(const float* __restrict__ values,
                           const int* __restrict__ lens,
                           const float* __restrict__ attn) {
    int b = blockIdx.x >> 5;
    int p = blockIdx.x & 31;
    int len = load_len(lens, b);
    int mstart = p * 64;
    int mend = min(mstart + 64, len);
    int tid = threadIdx.x;

    __shared__ float sw[64];
    float4 acc = make_float4(0.f, 0.f, 0.f, 0.f);
    if (mstart < mend) {
        if (tid < 64) {
            int mm = mstart + tid;
            sw[tid] = (mm < mend) ? attn[(size_t)b * NM + mm] : 0.f;
        }
        __syncthreads();
        const float4* vb4 = (const float4*)(values + (size_t)b * NM * ND);
        int lim = mend - mstart;
        #pragma unroll 8
        for (int t = 0; t < lim; ++t) {
            float w = sw[t];
            float4 v = __ldg(&vb4[(size_t)(mstart + t) * (ND / 4) + tid]);
            acc.x += w * v.x; acc.y += w * v.y;
            acc.z += w * v.z; acc.w += w * v.w;
        }
    }
    ((float4*)g_ctxp)[((size_t)b * 32 + p) * (ND / 4) + tid] = acc;
}

// ---------------- Kernel 5: reduce partials ------------------------------
__global__ void reduce_ctx_kernel() {
    int b = blockIdx.x;
    int d = threadIdx.x;
    float4 s = make_float4(0.f, 0.f, 0.f, 0.f);
    #pragma unroll
    for (int p = 0; p < 32; ++p) {
        float4 v = ((const float4*)g_ctxp)[((size_t)b * 32 + p) * (ND / 4) + d];
        s.x += v.x; s.y += v.y; s.z += v.z; s.w += v.w;
    }
    ((float4*)g_ctx)[(size_t)b * (ND / 4) + d] = s;
}

// ---------------- Kernel 6: output projection (Wk read once) -------------
__global__ void outproj_kernel(const float* __restrict__ Wk,
                               float* __restrict__ out) {
    int h = blockIdx.x * 8 + (threadIdx.x >> 5);
    int lane = threadIdx.x & 31;
    float wk[32];
    const float* wr = Wk + (size_t)h * ND;
    #pragma unroll
    for (int j = 0; j < 32; ++j) wk[j] = __ldg(&wr[lane + 32 * j]);
    for (int b = 0; b < NB; ++b) {
        const float* xr = g_ctx + (size_t)b * ND;
        float acc = 0.f;
        #pragma unroll
        for (int j = 0; j < 32; ++j) acc += xr[lane + 32 * j] * wk[j];
        #pragma unroll
        for (int o = 16; o; o >>= 1) acc += __shfl_down_sync(0xffffffffu, acc, o);
        if (lane == 0) out[b * ND + h] = acc;
    }
}

// ---------------- launch -------------------------------------------------
extern "C" void kernel_launch(void* const* d_in, const int* in_sizes, int n_in,
                              void* d_out, int out_size) {
    const float* queries = (const float*)d_in[0];
    const float* keys    = (const float*)d_in[1];
    const float* values  = (const float*)d_in[2];
    const int*   lens    = (const int*)d_in[3];
    const float* Wk      = (const float*)d_in[4];
    const float* Wq      = (const float*)d_in[5];
    const float* We      = (const float*)d_in[6];

    float* out      = (float*)d_out;
    float* out_val  = out;             // [B,1,D]
    float* out_attn = out + NB * ND;   // [B,1,M]

    static bool attr_set = false;
    if (!attr_set) {
        cudaFuncSetAttribute(score_kernel,
                             cudaFuncAttributeMaxDynamicSharedMemorySize, SC_SMEM);
        attr_set = true;
    }

    __nv_bfloat16* kbf;  cudaGetSymbolAddress((void**)&kbf, g_kbf);
    __nv_bfloat16* wkbf; cudaGetSymbolAddress((void**)&wkbf, g_wkbf);

    conv_keys_kernel<<<NB * 32, 256>>>(keys, kbf, lens);
    conv_kernel     <<<(ND * ND / 8 + 255) / 256, 256>>>(Wk, wkbf, ND * ND / 8);
    qproj_kernel    <<<ND / 8, 256>>>(queries, Wq);
    score_kernel    <<<dim3(NM / TM, NB), 256, SC_SMEM>>>(We, lens, out_attn);
    softmax_kernel  <<<NB, 256>>>(lens, out_attn);
    ctx_kernel      <<<NB * 32, 256>>>(values, lens, out_attn);
    reduce_ctx_kernel<<<NB, 256>>>();
    outproj_kernel  <<<ND / 8, 256>>>(Wk, out_val);
}

// round 15
// speedup vs baseline: 1.4841x; 1.0572x over previous
#include <cuda_runtime.h>
#include <cuda_bf16.h>
#include <cstdint>

#define NB 32
#define NM 2048
#define ND 1024
#define TM 256               // score m-tile
#define TH 128               // score h-tile
#define KE 64                // k elems per stage
#define NS 128               // stages = (ND/KE) * (ND/TH)
#define STRH 72              // smem row stride in halves (144B) -> conflict-free
#define A_ST (256 * STRH * 2)            // 36864
#define B_ST (128 * STRH * 2)            // 18432
#define STG (A_ST + B_ST)                // 55296
#define SC_SMEM (3 * STG)                // 165888

// scratch
__device__ float g_qp[NB * ND];
__device__ float g_ctx[NB * ND];
__device__ float g_ctxp[NB * 32 * ND];
__device__ __nv_bfloat16 g_kbf[(size_t)NB * NM * ND];   // keys in bf16
__device__ __nv_bfloat16 g_wkbf[ND * ND];               // W_key in bf16

// ---------------- helpers ------------------------------------------------
__device__ __forceinline__ int load_len(const int* __restrict__ L, int b) {
    bool is64 = (L[1] == 0) && (L[3] == 0) && (L[5] == 0);
    return is64 ? L[2 * b] : L[b];
}
__device__ __forceinline__ float tanh_fast(float x) {
    float r; asm("tanh.approx.f32 %0, %1;" : "=f"(r) : "f"(x)); return r;
}
__device__ __forceinline__ unsigned int smem_u32(const void* p) {
    unsigned int a;
    asm("{ .reg .u64 t; cvta.to.shared.u64 t, %1; cvt.u32.u64 %0, t; }" : "=r"(a) : "l"(p));
    return a;
}
__device__ __forceinline__ void cpasync16(unsigned int dst, const void* src) {
    asm volatile("cp.async.cg.shared.global [%0], [%1], 16;" :: "r"(dst), "l"(src) : "memory");
}
__device__ __forceinline__ void ldsm4(unsigned int& r0, unsigned int& r1,
                                      unsigned int& r2, unsigned int& r3,
                                      unsigned int addr) {
    asm volatile("ldmatrix.sync.aligned.m8n8.x4.shared.b16 {%0,%1,%2,%3}, [%4];"
                 : "=r"(r0), "=r"(r1), "=r"(r2), "=r"(r3) : "r"(addr));
}
__device__ __forceinline__ void mma_bf16(float d[4], const unsigned int a[4],
                                         const unsigned int b[2]) {
    asm volatile(
        "mma.sync.aligned.m16n8k16.row.col.f32.bf16.bf16.f32 "
        "{%0,%1,%2,%3}, {%4,%5,%6,%7}, {%8,%9}, {%0,%1,%2,%3};"
        : "+f"(d[0]), "+f"(d[1]), "+f"(d[2]), "+f"(d[3])
        : "r"(a[0]), "r"(a[1]), "r"(a[2]), "r"(a[3]), "r"(b[0]), "r"(b[1]));
}

// ---------------- Kernel 0: generic fp32 -> bf16 (for Wk) ----------------
__global__ void conv_kernel(const float* __restrict__ src,
                            __nv_bfloat16* __restrict__ dst, int n8) {
    int i = blockIdx.x * blockDim.x + threadIdx.x;
    if (i >= n8) return;
    const float4* s4 = (const float4*)src;
    float4 a = __ldg(&s4[2 * i]);
    float4 b = __ldg(&s4[2 * i + 1]);
    __nv_bfloat162 p0 = __float22bfloat162_rn(make_float2(a.x, a.y));
    __nv_bfloat162 p1 = __float22bfloat162_rn(make_float2(a.z, a.w));
    __nv_bfloat162 p2 = __float22bfloat162_rn(make_float2(b.x, b.y));
    __nv_bfloat162 p3 = __float22bfloat162_rn(make_float2(b.z, b.w));
    uint4 o;
    o.x = *(unsigned int*)&p0; o.y = *(unsigned int*)&p1;
    o.z = *(unsigned int*)&p2; o.w = *(unsigned int*)&p3;
    ((uint4*)dst)[i] = o;
}

// ---------------- Kernel 1: q projection (Wq read once) ------------------
__global__ void qproj_kernel(const float* __restrict__ q,
                             const float* __restrict__ Wq) {
    int h = blockIdx.x * 8 + (threadIdx.x >> 5);
    int lane = threadIdx.x & 31;
    float wq[32];
    const float* wr = Wq + (size_t)h * ND;
    #pragma unroll
    for (int j = 0; j < 32; ++j) wq[j] = __ldg(&wr[lane + 32 * j]);
    for (int b = 0; b < NB; ++b) {
        const float* qr = q + (size_t)b * ND;
        float acc = 0.f;
        #pragma unroll
        for (int j = 0; j < 32; ++j) acc += __ldg(&qr[lane + 32 * j]) * wq[j];
        #pragma unroll
        for (int o = 16; o; o >>= 1) acc += __shfl_down_sync(0xffffffffu, acc, o);
        if (lane == 0) g_qp[b * ND + h] = acc;
    }
}

// ---------------- Kernel 2: bf16 mma.sync score GEMM ---------------------
// 256m x 128h CTA tile, 16 warps as 4(m) x 4(n), warp tile 64x32.
// Fused prologue converts this CTA's keys rows fp32->bf16 (L2-resident).
__device__ __forceinline__ void load_stage(unsigned int sbase,
                                           const __nv_bfloat16* __restrict__ keysB,
                                           int m0, int s, int tid) {
    int hc = s >> 4, kt = s & 15, bf = s % 3;
    int k0 = kt * KE;
    unsigned int abase = sbase + bf * STG;
    unsigned int bbase = abase + A_ST;
    #pragma unroll
    for (int i = 0; i < 4; ++i) {
        int idx = i * 512 + tid;
        int r = idx >> 3, c = idx & 7;
        cpasync16(abase + (unsigned)(r * 144 + c * 16),
                  keysB + (size_t)(m0 + r) * ND + k0 + c * 8);
    }
    #pragma unroll
    for (int i = 0; i < 2; ++i) {
        int idx = i * 512 + tid;
        int r = idx >> 3, c = idx & 7;
        cpasync16(bbase + (unsigned)(r * 144 + c * 16),
                  g_wkbf + (size_t)(hc * 128 + r) * ND + k0 + c * 8);
    }
    asm volatile("cp.async.commit_group;" ::: "memory");
}

__global__ void __launch_bounds__(512, 1)
score_kernel(const float* __restrict__ keys,
             const float* __restrict__ We,
             const int* __restrict__ lens,
             float* __restrict__ attn_out) {
    int b = blockIdx.y;
    int m0 = blockIdx.x * TM;
    int len = load_len(lens, b);
    if (m0 >= len) return;

    extern __shared__ char smem[];
    unsigned int sbase = smem_u32(smem);
    int tid = threadIdx.x, lane = tid & 31, wid = tid >> 5;
    int wm = wid >> 2, wn = wid & 3;
    const __nv_bfloat16* keysB = g_kbf + (size_t)b * NM * ND;

    // ---- fused prologue: convert this CTA's 256 keys rows to bf16 ----
    {
        size_t base8 = (((size_t)b * NM + (size_t)m0) * ND) >> 3;
        const float4* s4 = (const float4*)keys;
        uint4* d4 = (uint4*)g_kbf;
        #pragma unroll 8
        for (int i = tid; i < TM * ND / 8; i += 512) {
            size_t j = base8 + i;
            float4 a = __ldg(&s4[2 * j]);
            float4 bb = __ldg(&s4[2 * j + 1]);
            __nv_bfloat162 p0 = __float22bfloat162_rn(make_float2(a.x, a.y));
            __nv_bfloat162 p1 = __float22bfloat162_rn(make_float2(a.z, a.w));
            __nv_bfloat162 p2 = __float22bfloat162_rn(make_float2(bb.x, bb.y));
            __nv_bfloat162 p3 = __float22bfloat162_rn(make_float2(bb.z, bb.w));
            uint4 o;
            o.x = *(unsigned int*)&p0; o.y = *(unsigned int*)&p1;
            o.z = *(unsigned int*)&p2; o.w = *(unsigned int*)&p3;
            d4[j] = o;
        }
    }
    __syncthreads();   // CTA-scope fence: STGs visible to our cp.async below

    // per-thread ldmatrix base offsets (bytes, stage-local)
    unsigned int aoff = (unsigned)((wm * 64 + (lane & 7) + ((lane >> 3) & 1) * 8) * 144
                                   + ((lane >> 4) & 1) * 16);
    unsigned int boff = (unsigned)(A_ST + (wn * 32 + (lane & 7) + ((lane >> 4) & 1) * 8) * 144
                                   + ((lane >> 3) & 1) * 16);

    float d[4][4][4];
    float sp[4][2];
    #pragma unroll
    for (int mf = 0; mf < 4; ++mf) { sp[mf][0] = 0.f; sp[mf][1] = 0.f; }

    load_stage(sbase, keysB, m0, 0, tid);
    load_stage(sbase, keysB, m0, 1, tid);

    for (int s = 0; s < NS; ++s) {
        if (s + 2 < NS) asm volatile("cp.async.wait_group 1;" ::: "memory");
        else            asm volatile("cp.async.wait_group 0;" ::: "memory");
        __syncthreads();
        if (s + 2 < NS) load_stage(sbase, keysB, m0, s + 2, tid);

        int bf = s % 3, kt = s & 15, hc = s >> 4;
        unsigned int stg = sbase + bf * STG;

        if (kt == 0) {
            #pragma unroll
            for (int mf = 0; mf < 4; ++mf)
                #pragma unroll
                for (int nf = 0; nf < 4; ++nf)
                    #pragma unroll
                    for (int e = 0; e < 4; ++e) d[mf][nf][e] = 0.f;
        }

        #pragma unroll
        for (int ks = 0; ks < 4; ++ks) {
            unsigned int cofs = (unsigned)(ks * 32);
            unsigned int ua[4][4], ub[4][2];
            #pragma unroll
            for (int mf = 0; mf < 4; ++mf)
                ldsm4(ua[mf][0], ua[mf][1], ua[mf][2], ua[mf][3],
                      stg + aoff + (unsigned)(mf * 16 * 144) + cofs);
            #pragma unroll
            for (int pr = 0; pr < 2; ++pr)
                ldsm4(ub[2 * pr][0], ub[2 * pr][1],
                      ub[2 * pr + 1][0], ub[2 * pr + 1][1],
                      stg + boff + (unsigned)(pr * 16 * 144) + cofs);
            #pragma unroll
            for (int mf = 0; mf < 4; ++mf)
                #pragma unroll
                for (int nf = 0; nf < 4; ++nf)
                    mma_bf16(d[mf][nf], ua[mf], ub[nf]);
        }

        if (kt == 15) {
            int hbase = hc * 128 + wn * 32 + 2 * (lane & 3);
            #pragma unroll
            for (int nf = 0; nf < 4; ++nf) {
                float qv0 = __ldg(&g_qp[b * ND + hbase + nf * 8]);
                float qv1 = __ldg(&g_qp[b * ND + hbase + nf * 8 + 1]);
                float we0 = __ldg(&We[hbase + nf * 8]);
                float we1 = __ldg(&We[hbase + nf * 8 + 1]);
                #pragma unroll
                for (int mf = 0; mf < 4; ++mf) {
                    sp[mf][0] += tanh_fast(d[mf][nf][0] + qv0) * we0;
                    sp[mf][0] += tanh_fast(d[mf][nf][1] + qv1) * we1;
                    sp[mf][1] += tanh_fast(d[mf][nf][2] + qv0) * we0;
                    sp[mf][1] += tanh_fast(d[mf][nf][3] + qv1) * we1;
                }
            }
        }
    }

    // cross-lane reduction via smem [256][17]
    __syncthreads();
    float* sred = (float*)smem;
    int col = wn * 4 + (lane & 3);
    #pragma unroll
    for (int mf = 0; mf < 4; ++mf)
        #pragma unroll
        for (int rb = 0; rb < 2; ++rb) {
            int r = wm * 64 + mf * 16 + (lane >> 2) + 8 * rb;
            sred[r * 17 + col] = sp[mf][rb];
        }
    __syncthreads();
    if (tid < 256) {
        float sacc = 0.f;
        #pragma unroll
        for (int j = 0; j < 16; ++j) sacc += sred[tid * 17 + j];
        attn_out[(size_t)b * NM + m0 + tid] = sacc;
    }
}

// ---------------- Kernel 3: masked softmax (in-place) --------------------
__global__ void softmax_kernel(const int* __restrict__ lens,
                               float* __restrict__ attn) {
    int b = blockIdx.x;
    int len = load_len(lens, b);
    float* row = attn + (size_t)b * NM;
    __shared__ float red[256];
    int tid = threadIdx.x;

    float mx = -3.0e38f;
    for (int m = tid; m < len; m += 256) mx = fmaxf(mx, row[m]);
    red[tid] = mx; __syncthreads();
    for (int s = 128; s; s >>= 1) {
        if (tid < s) red[tid] = fmaxf(red[tid], red[tid + s]);
        __syncthreads();
    }
    mx = red[0]; __syncthreads();

    float sm = 0.f;
    for (int m = tid; m < len; m += 256) sm += expf(row[m] - mx);
    red[tid] = sm; __syncthreads();
    for (int s = 128; s; s >>= 1) {
        if (tid < s) red[tid] += red[tid + s];
        __syncthreads();
    }
    float inv = 1.f / red[0];
    __syncthreads();

    for (int m = tid; m < NM; m += 256) {
        float w = (m < len) ? expf(row[m] - mx) * inv : 0.f;
        row[m] = w;
    }
}

// ---------------- Kernel 4: ctx partials (32 chunks x 64 rows, float4) ---
__global__ void ctx_kernel(const float* __restrict__ values,
                           const int* __restrict__ lens,
                           const float* __restrict__ attn) {
    int b = blockIdx.x >> 5;
    int p = blockIdx.x & 31;
    int len = load_len(lens, b);
    int mstart = p * 64;
    int mend = min(mstart + 64, len);
    int tid = threadIdx.x;

    __shared__ float sw[64];
    float4 acc = make_float4(0.f, 0.f, 0.f, 0.f);
    if (mstart < mend) {
        if (tid < 64) {
            int mm = mstart + tid;
            sw[tid] = (mm < mend) ? attn[(size_t)b * NM + mm] : 0.f;
        }
        __syncthreads();
        const float4* vb4 = (const float4*)(values + (size_t)b * NM * ND);
        int lim = mend - mstart;
        #pragma unroll 8
        for (int t = 0; t < lim; ++t) {
            float w = sw[t];
            float4 v = __ldg(&vb4[(size_t)(mstart + t) * (ND / 4) + tid]);
            acc.x += w * v.x; acc.y += w * v.y;
            acc.z += w * v.z; acc.w += w * v.w;
        }
    }
    ((float4*)g_ctxp)[((size_t)b * 32 + p) * (ND / 4) + tid] = acc;
}

// ---------------- Kernel 5: reduce partials ------------------------------
__global__ void reduce_ctx_kernel() {
    int b = blockIdx.x;
    int d = threadIdx.x;
    float4 s = make_float4(0.f, 0.f, 0.f, 0.f);
    #pragma unroll
    for (int p = 0; p < 32; ++p) {
        float4 v = ((const float4*)g_ctxp)[((size_t)b * 32 + p) * (ND / 4) + d];
        s.x += v.x; s.y += v.y; s.z += v.z; s.w += v.w;
    }
    ((float4*)g_ctx)[(size_t)b * (ND / 4) + d] = s;
}

// ---------------- Kernel 6: output projection (Wk read once) -------------
__global__ void outproj_kernel(const float* __restrict__ Wk,
                               float* __restrict__ out) {
    int h = blockIdx.x * 8 + (threadIdx.x >> 5);
    int lane = threadIdx.x & 31;
    float wk[32];
    const float* wr = Wk + (size_t)h * ND;
    #pragma unroll
    for (int j = 0; j < 32; ++j) wk[j] = __ldg(&wr[lane + 32 * j]);
    for (int b = 0; b < NB; ++b) {
        const float* xr = g_ctx + (size_t)b * ND;
        float acc = 0.f;
        #pragma unroll
        for (int j = 0; j < 32; ++j) acc += xr[lane + 32 * j] * wk[j];
        #pragma unroll
        for (int o = 16; o; o >>= 1) acc += __shfl_down_sync(0xffffffffu, acc, o);
        if (lane == 0) out[b * ND + h] = acc;
    }
}

// ---------------- launch -------------------------------------------------
extern "C" void kernel_launch(void* const* d_in, const int* in_sizes, int n_in,
                              void* d_out, int out_size) {
    const float* queries = (const float*)d_in[0];
    const float* keys    = (const float*)d_in[1];
    const float* values  = (const float*)d_in[2];
    const int*   lens    = (const int*)d_in[3];
    const float* Wk      = (const float*)d_in[4];
    const float* Wq      = (const float*)d_in[5];
    const float* We      = (const float*)d_in[6];

    float* out      = (float*)d_out;
    float* out_val  = out;             // [B,1,D]
    float* out_attn = out + NB * ND;   // [B,1,M]

    static bool attr_set = false;
    if (!attr_set) {
        cudaFuncSetAttribute(score_kernel,
                             cudaFuncAttributeMaxDynamicSharedMemorySize, SC_SMEM);
        attr_set = true;
    }

    __nv_bfloat16* wkbf; cudaGetSymbolAddress((void**)&wkbf, g_wkbf);

    conv_kernel     <<<(ND * ND / 8 + 255) / 256, 256>>>(Wk, wkbf, ND * ND / 8);
    qproj_kernel    <<<ND / 8, 256>>>(queries, Wq);
    score_kernel    <<<dim3(NM / TM, NB), 512, SC_SMEM>>>(keys, We, lens, out_attn);
    softmax_kernel  <<<NB, 256>>>(lens, out_attn);
    ctx_kernel      <<<NB * 32, 256>>>(values, lens, out_attn);
    reduce_ctx_kernel<<<NB, 256>>>();
    outproj_kernel  <<<ND / 8, 256>>>(Wk, out_val);
}